// round 6
// baseline (speedup 1.0000x reference)
#include <cuda_runtime.h>

// B=4, S=1024, P=1024, E=1024, H=16, D=64, NS=2048
// out = [4,1024,1024] f32, present = [2,4,16,2048,64] f32 (packed after out)

__device__ float g_q[4096 * 1024];               // tf32, pre-scaled Q
__device__ float g_attn[4096 * 1024];            // tf32-rounded attn output
__device__ float g_kvt[2 * 4 * 16 * 2048 * 64];  // tf32-rounded K/V, present layout
__device__ float g_xr[4096 * 1024];              // tf32-rounded x
__device__ float g_wat[1024 * 3072];             // tf32-rounded w_attn
__device__ float g_wpr[1024 * 1024];             // tf32-rounded w_proj

#define LOG2E 1.44269504088896f

__device__ __forceinline__ unsigned f2tf(float x) {
    unsigned u;
    asm("cvt.rna.tf32.f32 %0, %1;" : "=r"(u) : "f"(x));
    return u;
}
__device__ __forceinline__ float ex2(float x) {
    float y;
    asm("ex2.approx.ftz.f32 %0, %1;" : "=f"(y) : "f"(x));
    return y;
}
__device__ __forceinline__ void mma_tf32(float c[4], unsigned a0, unsigned a1,
                                         unsigned a2, unsigned a3,
                                         unsigned b0, unsigned b1) {
    asm volatile(
        "mma.sync.aligned.m16n8k8.row.col.f32.tf32.tf32.f32 "
        "{%0,%1,%2,%3}, {%4,%5,%6,%7}, {%8,%9}, {%0,%1,%2,%3};\n"
        : "+f"(c[0]), "+f"(c[1]), "+f"(c[2]), "+f"(c[3])
        : "r"(a0), "r"(a1), "r"(a2), "r"(a3), "r"(b0), "r"(b1));
}
__device__ __forceinline__ void cp16(unsigned dst_smem, const void* src) {
    asm volatile("cp.async.ca.shared.global [%0], [%1], 16;\n"
                 :: "r"(dst_smem), "l"(src));
}
__device__ __forceinline__ void cp_commit() {
    asm volatile("cp.async.commit_group;\n");
}
__device__ __forceinline__ void cp_wait1() {
    asm volatile("cp.async.wait_group 1;\n");
}
__device__ __forceinline__ void cp_wait2() {
    asm volatile("cp.async.wait_group 2;\n");
}

// ---------------------------------------------------------------------------
// Elementwise tf32 pre-rounding (float4 grid-stride-free, exact size grids)
// ---------------------------------------------------------------------------
__global__ __launch_bounds__(256) void round_tf32_kernel(
    const float* __restrict__ in, float* __restrict__ out)
{
    int i = blockIdx.x * 256 + threadIdx.x;
    float4 v = *(const float4*)&in[(long)i * 4];
    float4 r;
    r.x = __uint_as_float(f2tf(v.x));
    r.y = __uint_as_float(f2tf(v.y));
    r.z = __uint_as_float(f2tf(v.z));
    r.w = __uint_as_float(f2tf(v.w));
    *(float4*)&out[(long)i * 4] = r;
}

// ---------------------------------------------------------------------------
// tf32 GEMM v2: pre-rounded operands, cp.async 4-stage, BK=16.
// Block 128x128, 8 warps (2x4), warp tile 64x32.
// As[stage][m][PA=20] (row-major m,k), Bs[stage][k][PB=136].
// mode 0: C = A@B + bias (fp32)
// mode 1: QKV split epilogue -> g_q (scaled tf32) / present (fp32) / kvt (tf32)
// ---------------------------------------------------------------------------
#define PA 20
#define PB 136
#define NSTG 4
#define A_TILE (128 * PA)
#define B_TILE (16 * PB)

__global__ __launch_bounds__(256, 2) void gemm2_kernel(
    const float* __restrict__ A, const float* __restrict__ B,
    const float* __restrict__ bias, float* __restrict__ C,
    float* __restrict__ present, float* __restrict__ kvt,
    int M, int N, int K, int mode)
{
    extern __shared__ float smem[];
    float* As = smem;                  // [NSTG][A_TILE]
    float* Bs = smem + NSTG * A_TILE;  // [NSTG][B_TILE]

    const int tid = threadIdx.x;
    const int lane = tid & 31;
    const int wid = tid >> 5;
    const int wm = wid & 1;
    const int wn = wid >> 1;
    const int bm = blockIdx.y * 128;
    const int bn = blockIdx.x * 128;

    const unsigned as_base = (unsigned)__cvta_generic_to_shared(As);
    const unsigned bs_base = (unsigned)__cvta_generic_to_shared(Bs);

    const int nIter = K / 16;

    auto stage = [&](int it) {
        const float* Ab = A + (long)bm * K + it * 16;
        const float* Bb = B + (long)(it * 16) * N + bn;
        unsigned ad = as_base + (unsigned)((it & (NSTG - 1)) * A_TILE * 4);
        unsigned bd = bs_base + (unsigned)((it & (NSTG - 1)) * B_TILE * 4);
#pragma unroll
        for (int l = 0; l < 2; ++l) {
            int idx = l * 256 + tid;            // 512 A chunks
            int r = idx >> 2, kc = (idx & 3) * 4;
            cp16(ad + (unsigned)((r * PA + kc) * 4), Ab + (long)r * K + kc);
            int rk = idx >> 5, nc = (idx & 31) * 4;  // 512 B chunks
            cp16(bd + (unsigned)((rk * PB + nc) * 4), Bb + (long)rk * N + nc);
        }
    };

    for (int it = 0; it < 3; ++it) {
        stage(it);
        cp_commit();
    }

    float acc[4][4][4] = {};

    for (int it = 0; it < nIter; ++it) {
        cp_wait2();
        __syncthreads();
        if (it + 3 < nIter) stage(it + 3);
        cp_commit();

        const float* Ab = As + (it & (NSTG - 1)) * A_TILE;
        const float* Bb = Bs + (it & (NSTG - 1)) * B_TILE;

#pragma unroll
        for (int kh = 0; kh < 2; ++kh) {
            const int k = kh * 8 + (lane & 3);
            unsigned af[4][4];
#pragma unroll
            for (int mt = 0; mt < 4; ++mt) {
                int m = wm * 64 + mt * 16 + (lane >> 2);
                af[mt][0] = __float_as_uint(Ab[m * PA + k]);
                af[mt][1] = __float_as_uint(Ab[(m + 8) * PA + k]);
                af[mt][2] = __float_as_uint(Ab[m * PA + k + 4]);
                af[mt][3] = __float_as_uint(Ab[(m + 8) * PA + k + 4]);
            }
#pragma unroll
            for (int nt = 0; nt < 4; ++nt) {
                int n = wn * 32 + nt * 8 + (lane >> 2);
                unsigned b0 = __float_as_uint(Bb[k * PB + n]);
                unsigned b1 = __float_as_uint(Bb[(k + 4) * PB + n]);
#pragma unroll
                for (int mt = 0; mt < 4; ++mt)
                    mma_tf32(acc[mt][nt], af[mt][0], af[mt][1], af[mt][2], af[mt][3], b0, b1);
            }
        }
        __syncthreads();
    }

    // epilogue
    const int kvsel = (bn >= 2048) ? 1 : 0;
#pragma unroll
    for (int mt = 0; mt < 4; ++mt) {
        int row0 = bm + wm * 64 + mt * 16 + (lane >> 2);
#pragma unroll
        for (int nt = 0; nt < 4; ++nt) {
            int col = bn + wn * 32 + nt * 8 + 2 * (lane & 3);
            float2 bv = *(const float2*)&bias[col];
            float v00 = acc[mt][nt][0] + bv.x, v01 = acc[mt][nt][1] + bv.y;
            float v10 = acc[mt][nt][2] + bv.x, v11 = acc[mt][nt][3] + bv.y;
            if (mode == 0) {
                float2 r0 = {v00, v01}, r1 = {v10, v11};
                *(float2*)&C[(long)row0 * N + col] = r0;
                *(float2*)&C[(long)(row0 + 8) * N + col] = r1;
            } else if (bn < 1024) {
                const float sc = 0.125f * LOG2E;
                float2 r0, r1;
                r0.x = __uint_as_float(f2tf(v00 * sc));
                r0.y = __uint_as_float(f2tf(v01 * sc));
                r1.x = __uint_as_float(f2tf(v10 * sc));
                r1.y = __uint_as_float(f2tf(v11 * sc));
                *(float2*)&C[(long)row0 * 1024 + col] = r0;
                *(float2*)&C[(long)(row0 + 8) * 1024 + col] = r1;
            } else {
                int colk = col - 1024 - (kvsel << 10);
                int h = colk >> 6, d = colk & 63;
                int b = row0 >> 10, s = row0 & 1023;
                long o0 = ((((long)(kvsel * 4 + b) * 16 + h) * 2048) + 1024 + s) * 64 + d;
                long o1 = o0 + 8 * 64;
                float2 p0 = {v00, v01}, p1 = {v10, v11};
                *(float2*)&present[o0] = p0;
                *(float2*)&present[o1] = p1;
                float2 t0, t1;
                t0.x = __uint_as_float(f2tf(v00));
                t0.y = __uint_as_float(f2tf(v01));
                t1.x = __uint_as_float(f2tf(v10));
                t1.y = __uint_as_float(f2tf(v11));
                *(float2*)&kvt[o0] = t0;
                *(float2*)&kvt[o1] = t1;
            }
        }
    }
}

// ---------------------------------------------------------------------------
// Copy the PAST half of present (+ rounded copy). New half written by gemm2.
// ---------------------------------------------------------------------------
__global__ __launch_bounds__(256) void copy_past_kernel(
    const float* __restrict__ past, float* __restrict__ present,
    float* __restrict__ kvt)
{
    int i4 = blockIdx.x * 256 + threadIdx.x;  // 0 .. 2097151
    int d4 = i4 & 15;
    int t = i4 >> 4;
    int p = t & 1023; t >>= 10;
    int h = t & 15;   t >>= 4;
    int b = t & 3;    t >>= 2;
    int kv = t;

    float4 v = *(const float4*)&past[(((long)(kv * 4 + b) * 16 + h) * 1024 + p) * 64 + d4 * 4];
    long dst = ((((long)(kv * 4 + b) * 16 + h) * 2048) + p) * 64 + d4 * 4;
    *(float4*)&present[dst] = v;
    float4 r;
    r.x = __uint_as_float(f2tf(v.x));
    r.y = __uint_as_float(f2tf(v.y));
    r.z = __uint_as_float(f2tf(v.z));
    r.w = __uint_as_float(f2tf(v.w));
    *(float4*)&kvt[dst] = r;
}

// ---------------------------------------------------------------------------
// Flash attention, tf32 mma, cp.async K/V double buffer + cp.async Q (g_q is
// pre-scaled, pre-rounded). Epilogue writes tf32-rounded g_attn.
// ---------------------------------------------------------------------------
#define QKP 68
#define VST 72

__global__ __launch_bounds__(256, 2) void attn_kernel(
    const float* __restrict__ gq,
    const float* __restrict__ kvt,
    float* __restrict__ aout)
{
    extern __shared__ float sm[];
    float* Qs = sm;                         // [128][68]
    float* Ks = Qs + 128 * QKP;             // [2][64][68]
    float* Vs = Ks + 2 * 64 * QKP;          // [2][64][72]

    const int tid = threadIdx.x;
    const int lane = tid & 31;
    const int w = tid >> 5;
    const int qt = blockIdx.x & 7;
    const int h  = (blockIdx.x >> 3) & 15;
    const int b  = blockIdx.x >> 7;

    const float* kbase = kvt + (long)(b * 16 + h) * (2048 * 64);
    const float* vbase = kbase + (long)4 * 16 * 2048 * 64;

    const unsigned qs_base = (unsigned)__cvta_generic_to_shared(Qs);
    const unsigned ks_base = (unsigned)__cvta_generic_to_shared(Ks);
    const unsigned vs_base = (unsigned)__cvta_generic_to_shared(Vs);

    auto stage = [&](int kt, int bf) {
        const float* kp = kbase + (long)kt * 64 * 64;
        const float* vp = vbase + (long)kt * 64 * 64;
        unsigned kd = ks_base + (unsigned)(bf * 64 * QKP * 4);
        unsigned vd = vs_base + (unsigned)(bf * 64 * VST * 4);
#pragma unroll
        for (int l = 0; l < 4; ++l) {
            int idx = l * 256 + tid;
            int r = idx >> 4, c4 = (idx & 15) * 4;
            cp16(kd + (unsigned)((r * QKP + c4) * 4), kp + idx * 4);
            cp16(vd + (unsigned)((r * VST + c4) * 4), vp + idx * 4);
        }
    };

    // Q tile via cp.async (pre-scaled/rounded)
    {
        const float* qb = gq + ((long)b * 1024 + qt * 128) * 1024 + h * 64;
#pragma unroll
        for (int l = 0; l < 8; ++l) {
            int idx = l * 256 + tid;
            int r = idx >> 4, c4 = (idx & 15) * 4;
            cp16(qs_base + (unsigned)((r * QKP + c4) * 4), qb + (long)r * 1024 + c4);
        }
    }
    stage(0, 0); cp_commit();      // group0: Q + KV0
    stage(1, 1); cp_commit();      // group1: KV1
    cp_wait1();
    __syncthreads();

    const int diag0 = 16 + 2 * qt;
    const int nkt = diag0 + 2;

    // Hoist Q fragments
    unsigned qf[8][4];
    {
        int r = 16 * w + (lane >> 2);
#pragma unroll
        for (int kk = 0; kk < 8; ++kk) {
            int k = kk * 8 + (lane & 3);
            qf[kk][0] = __float_as_uint(Qs[r * QKP + k]);
            qf[kk][1] = __float_as_uint(Qs[(r + 8) * QKP + k]);
            qf[kk][2] = __float_as_uint(Qs[r * QKP + k + 4]);
            qf[kk][3] = __float_as_uint(Qs[(r + 8) * QKP + k + 4]);
        }
    }

    float o[8][4] = {};
    float m0 = -1e30f, m1 = -1e30f, l0 = 0.f, l1 = 0.f;

    const int src_a = (lane & ~3) | ((lane & 3) >> 1);
    const int src_b = src_a + 2;

    for (int kt = 0; kt < nkt; ++kt) {
        const int bf = kt & 1;
        const float* Kb = Ks + bf * 64 * QKP;
        const float* Vb = Vs + bf * 64 * VST;

        float s[8][4] = {};
#pragma unroll
        for (int kk = 0; kk < 8; ++kk) {
            int k = kk * 8 + (lane & 3);
#pragma unroll
            for (int nt = 0; nt < 8; ++nt) {
                int n = nt * 8 + (lane >> 2);
                unsigned b0 = __float_as_uint(Kb[n * QKP + k]);
                unsigned b1 = __float_as_uint(Kb[n * QKP + k + 4]);
                mma_tf32(s[nt], qf[kk][0], qf[kk][1], qf[kk][2], qf[kk][3], b0, b1);
            }
        }

        if (kt >= diag0) {
            int q0 = 1024 + qt * 128 + 16 * w + (lane >> 2);
            int q1 = q0 + 8;
#pragma unroll
            for (int nt = 0; nt < 8; ++nt) {
                int kc = kt * 64 + nt * 8 + 2 * (lane & 3);
                if (kc > q0)     s[nt][0] = -14427.0f;
                if (kc + 1 > q0) s[nt][1] = -14427.0f;
                if (kc > q1)     s[nt][2] = -14427.0f;
                if (kc + 1 > q1) s[nt][3] = -14427.0f;
            }
        }

        {
            float mt0 = -1e30f, mt1 = -1e30f;
#pragma unroll
            for (int nt = 0; nt < 8; ++nt) {
                mt0 = fmaxf(mt0, fmaxf(s[nt][0], s[nt][1]));
                mt1 = fmaxf(mt1, fmaxf(s[nt][2], s[nt][3]));
            }
            mt0 = fmaxf(mt0, __shfl_xor_sync(0xffffffffu, mt0, 1));
            mt0 = fmaxf(mt0, __shfl_xor_sync(0xffffffffu, mt0, 2));
            mt1 = fmaxf(mt1, __shfl_xor_sync(0xffffffffu, mt1, 1));
            mt1 = fmaxf(mt1, __shfl_xor_sync(0xffffffffu, mt1, 2));
            float mn0 = fmaxf(m0, mt0), mn1 = fmaxf(m1, mt1);
            float c0 = ex2(m0 - mn0), c1 = ex2(m1 - mn1);
            m0 = mn0; m1 = mn1;
            float rs0 = 0.f, rs1 = 0.f;
#pragma unroll
            for (int nt = 0; nt < 8; ++nt) {
                s[nt][0] = ex2(s[nt][0] - mn0);
                s[nt][1] = ex2(s[nt][1] - mn0);
                s[nt][2] = ex2(s[nt][2] - mn1);
                s[nt][3] = ex2(s[nt][3] - mn1);
                rs0 += s[nt][0] + s[nt][1];
                rs1 += s[nt][2] + s[nt][3];
            }
            rs0 += __shfl_xor_sync(0xffffffffu, rs0, 1);
            rs0 += __shfl_xor_sync(0xffffffffu, rs0, 2);
            rs1 += __shfl_xor_sync(0xffffffffu, rs1, 1);
            rs1 += __shfl_xor_sync(0xffffffffu, rs1, 2);
            l0 = l0 * c0 + rs0;
            l1 = l1 * c1 + rs1;
#pragma unroll
            for (int dt = 0; dt < 8; ++dt) {
                o[dt][0] *= c0; o[dt][1] *= c0;
                o[dt][2] *= c1; o[dt][3] *= c1;
            }
        }

        // O += P @ V (A-frags via shuffles)
#pragma unroll
        for (int kk = 0; kk < 8; ++kk) {
            float x0 = __shfl_sync(0xffffffffu, s[kk][0], src_a);
            float x1 = __shfl_sync(0xffffffffu, s[kk][1], src_a);
            float y0 = __shfl_sync(0xffffffffu, s[kk][2], src_a);
            float y1 = __shfl_sync(0xffffffffu, s[kk][3], src_a);
            float z0 = __shfl_sync(0xffffffffu, s[kk][0], src_b);
            float z1 = __shfl_sync(0xffffffffu, s[kk][1], src_b);
            float u0 = __shfl_sync(0xffffffffu, s[kk][2], src_b);
            float u1 = __shfl_sync(0xffffffffu, s[kk][3], src_b);
            bool odd = (lane & 1);
            unsigned a0 = f2tf(odd ? x1 : x0);
            unsigned a1 = f2tf(odd ? y1 : y0);
            unsigned a2 = f2tf(odd ? z1 : z0);
            unsigned a3 = f2tf(odd ? u1 : u0);
            int kb0 = (kk * 8 + (lane & 3)) * VST;
            int kb1 = (kk * 8 + (lane & 3) + 4) * VST;
#pragma unroll
            for (int dt = 0; dt < 8; ++dt) {
                int n = dt * 8 + (lane >> 2);
                unsigned b0 = __float_as_uint(Vb[kb0 + n]);
                unsigned b1 = __float_as_uint(Vb[kb1 + n]);
                mma_tf32(o[dt], a0, a1, a2, a3, b0, b1);
            }
        }

        if (kt + 1 < nkt) {
            __syncthreads();
            if (kt + 2 < nkt) stage(kt + 2, bf);
            cp_commit();
            cp_wait1();
            __syncthreads();
        }
    }

    // epilogue: normalized, tf32-rounded for proj GEMM
    {
        float inv0 = 1.0f / l0, inv1 = 1.0f / l1;
        int row0 = b * 1024 + qt * 128 + 16 * w + (lane >> 2);
        float* ob = aout + (long)row0 * 1024 + h * 64;
#pragma unroll
        for (int dt = 0; dt < 8; ++dt) {
            int c = dt * 8 + 2 * (lane & 3);
            float2 v0, v1;
            v0.x = __uint_as_float(f2tf(o[dt][0] * inv0));
            v0.y = __uint_as_float(f2tf(o[dt][1] * inv0));
            v1.x = __uint_as_float(f2tf(o[dt][2] * inv1));
            v1.y = __uint_as_float(f2tf(o[dt][3] * inv1));
            *(float2*)&ob[c] = v0;
            *(float2*)&ob[(long)8 * 1024 + c] = v1;
        }
    }
}

// ---------------------------------------------------------------------------
extern "C" void kernel_launch(void* const* d_in, const int* in_sizes, int n_in,
                              void* d_out, int out_size)
{
    const float* x      = (const float*)d_in[0];
    const float* past   = (const float*)d_in[1];
    const float* w_attn = (const float*)d_in[2];
    const float* b_attn = (const float*)d_in[3];
    const float* w_proj = (const float*)d_in[4];
    const float* b_proj = (const float*)d_in[5];

    float* out = (float*)d_out;
    float* present = out + 4194304;

    float *q_p, *attn_p, *kvt_p, *xr_p, *wat_p, *wpr_p;
    cudaGetSymbolAddress((void**)&q_p, g_q);
    cudaGetSymbolAddress((void**)&attn_p, g_attn);
    cudaGetSymbolAddress((void**)&kvt_p, g_kvt);
    cudaGetSymbolAddress((void**)&xr_p, g_xr);
    cudaGetSymbolAddress((void**)&wat_p, g_wat);
    cudaGetSymbolAddress((void**)&wpr_p, g_wpr);

    // 0) pre-round GEMM operands to tf32
    round_tf32_kernel<<<4096, 256>>>(x, xr_p);
    round_tf32_kernel<<<3072, 256>>>(w_attn, wat_p);
    round_tf32_kernel<<<1024, 256>>>(w_proj, wpr_p);

    int gemm_smem = (NSTG * A_TILE + NSTG * B_TILE) * (int)sizeof(float);
    static int gemm_attr_set = 0;
    cudaFuncSetAttribute(gemm2_kernel,
                         cudaFuncAttributeMaxDynamicSharedMemorySize, gemm_smem);

    // 1) QKV projection with fused Q-scale / present / kvt epilogue
    {
        dim3 grid(3072 / 128, 4096 / 128);
        gemm2_kernel<<<grid, 256, gemm_smem>>>(xr_p, wat_p, b_attn, q_p,
                                               present, kvt_p, 4096, 3072, 1024, 1);
    }

    // 2) past half of present/kvt
    copy_past_kernel<<<2097152 / 256, 256>>>(past, present, kvt_p);

    // 3) attention
    {
        int smem = (128 * QKP + 2 * 64 * QKP + 2 * 64 * VST) * (int)sizeof(float);
        cudaFuncSetAttribute(attn_kernel,
                             cudaFuncAttributeMaxDynamicSharedMemorySize, smem);
        attn_kernel<<<512, 256, smem>>>(q_p, kvt_p, attn_p);
    }

    // 4) output projection
    {
        dim3 grid(1024 / 128, 4096 / 128);
        gemm2_kernel<<<grid, 256, gemm_smem>>>(attn_p, wpr_p, b_proj, out,
                                               nullptr, nullptr, 4096, 1024, 1024, 0);
    }
}

// round 7
// speedup vs baseline: 1.5148x; 1.5148x over previous
#include <cuda_runtime.h>

// B=4, S=1024, P=1024, E=1024, H=16, D=64, NS=2048
// out = [4,1024,1024] f32, present = [2,4,16,2048,64] f32 (packed after out)

__device__ float g_q[4096 * 1024];               // tf32, pre-scaled Q
__device__ float g_attn[4096 * 1024];            // tf32-rounded attn output
__device__ float g_kvt[2 * 4 * 16 * 2048 * 64];  // tf32-rounded K/V, present layout
__device__ float g_xr[4096 * 1024];              // tf32-rounded x
__device__ float g_wat[1024 * 3072];             // tf32-rounded w_attn
__device__ float g_wpr[1024 * 1024];             // tf32-rounded w_proj

#define LOG2E 1.44269504088896f

__device__ __forceinline__ unsigned f2tf(float x) {
    unsigned u;
    asm("cvt.rna.tf32.f32 %0, %1;" : "=r"(u) : "f"(x));
    return u;
}
__device__ __forceinline__ float ex2(float x) {
    float y;
    asm("ex2.approx.ftz.f32 %0, %1;" : "=f"(y) : "f"(x));
    return y;
}
__device__ __forceinline__ void mma_tf32(float c[4], unsigned a0, unsigned a1,
                                         unsigned a2, unsigned a3,
                                         unsigned b0, unsigned b1) {
    asm volatile(
        "mma.sync.aligned.m16n8k8.row.col.f32.tf32.tf32.f32 "
        "{%0,%1,%2,%3}, {%4,%5,%6,%7}, {%8,%9}, {%0,%1,%2,%3};\n"
        : "+f"(c[0]), "+f"(c[1]), "+f"(c[2]), "+f"(c[3])
        : "r"(a0), "r"(a1), "r"(a2), "r"(a3), "r"(b0), "r"(b1));
}
__device__ __forceinline__ void ldsm4(unsigned& r0, unsigned& r1,
                                      unsigned& r2, unsigned& r3, unsigned addr) {
    asm volatile("ldmatrix.sync.aligned.m8n8.x4.shared.b16 {%0,%1,%2,%3}, [%4];"
                 : "=r"(r0), "=r"(r1), "=r"(r2), "=r"(r3) : "r"(addr));
}
__device__ __forceinline__ void cp16(unsigned dst_smem, const void* src) {
    asm volatile("cp.async.ca.shared.global [%0], [%1], 16;\n"
                 :: "r"(dst_smem), "l"(src));
}
__device__ __forceinline__ void cp_commit() {
    asm volatile("cp.async.commit_group;\n");
}
__device__ __forceinline__ void cp_wait1() {
    asm volatile("cp.async.wait_group 1;\n");
}

// ---------------------------------------------------------------------------
// Elementwise tf32 pre-rounding
// ---------------------------------------------------------------------------
__global__ __launch_bounds__(256) void round_tf32_kernel(
    const float* __restrict__ in, float* __restrict__ out)
{
    int i = blockIdx.x * 256 + threadIdx.x;
    float4 v = *(const float4*)&in[(long)i * 4];
    float4 r;
    r.x = __uint_as_float(f2tf(v.x));
    r.y = __uint_as_float(f2tf(v.y));
    r.z = __uint_as_float(f2tf(v.z));
    r.w = __uint_as_float(f2tf(v.w));
    *(float4*)&out[(long)i * 4] = r;
}

// ---------------------------------------------------------------------------
// tf32 GEMM v3: pre-rounded operands, R2 scheduling (register prefetch,
// single barrier/iter, 2-buffer), A fragments via ldmatrix.x4.
// As: row-major [m][16], XOR-swizzled 4-float chunks: chunk ^= (m&6)>>1.
// Bs: [k][n] stride 136 (R2 layout). Block 128x128, BK=16, 8 warps (2x4).
// mode 0: C = A@B + bias (fp32)
// mode 1: QKV split epilogue -> g_q (scaled tf32) / present (fp32) / kvt (tf32)
// ---------------------------------------------------------------------------
#define PB 136
__global__ __launch_bounds__(256, 2) void gemm3_kernel(
    const float* __restrict__ A, const float* __restrict__ B,
    const float* __restrict__ bias, float* __restrict__ C,
    float* __restrict__ present, float* __restrict__ kvt,
    int M, int N, int K, int mode)
{
    __shared__ float As[2][128 * 16];
    __shared__ float Bs[2][16 * PB];

    const int tid = threadIdx.x;
    const int lane = tid & 31;
    const int wid = tid >> 5;
    const int wm = wid & 1;
    const int wn = wid >> 1;
    const int bm = blockIdx.y * 128;
    const int bn = blockIdx.x * 128;

    // staging coords
    const int ar = tid >> 1;            // A row 0..127
    const int ac = (tid & 1) << 3;      // k offset 0 or 8
    const int bk = tid >> 4;            // B k-row 0..15
    const int bnc = (tid & 15) << 3;    // B n offset

    const float* Ap = A + (long)(bm + ar) * K + ac;
    const float* Bp = B + (long)bk * N + bn + bnc;

    // A store offsets (swizzled)
    const int axor = (ar & 6) >> 1;
    const int ast0 = ar * 16 + 4 * (((ac >> 2) + 0) ^ axor);
    const int ast1 = ar * 16 + 4 * (((ac >> 2) + 1) ^ axor);

    // ldmatrix addresses: per (mt, kh), lane supplies row m = wm*64+mt*16+lrow,
    // chunk = (2*kh + lhi) ^ ((lrow&6)>>1)
    const int lrow = lane & 15;
    const int lhi = lane >> 4;
    const int lxor = (lrow & 6) >> 1;
    const unsigned as_base = (unsigned)__cvta_generic_to_shared(&As[0][0]);
    unsigned amat[4][2];
#pragma unroll
    for (int mt = 0; mt < 4; ++mt)
#pragma unroll
        for (int kh = 0; kh < 2; ++kh) {
            int m = wm * 64 + mt * 16 + lrow;
            int ch = (2 * kh + lhi) ^ lxor;
            amat[mt][kh] = as_base + (unsigned)((m * 16 + 4 * ch) * 4);
        }

    float acc[4][4][4] = {};

    // preload tile 0
    float4 av0 = *(const float4*)Ap;
    float4 av1 = *(const float4*)(Ap + 4);
    float4 bv0 = *(const float4*)Bp;
    float4 bv1 = *(const float4*)(Bp + 4);

    int buf = 0;
    *(float4*)&As[0][ast0] = av0;
    *(float4*)&As[0][ast1] = av1;
    *(float4*)&Bs[0][bk * PB + bnc] = bv0;
    *(float4*)&Bs[0][bk * PB + bnc + 4] = bv1;
    __syncthreads();

    const int nIter = K / 16;
    for (int it = 0; it < nIter; ++it) {
        if (it + 1 < nIter) {
            Ap += 16;
            Bp += (long)16 * N;
            av0 = *(const float4*)Ap;
            av1 = *(const float4*)(Ap + 4);
            bv0 = *(const float4*)Bp;
            bv1 = *(const float4*)(Bp + 4);
        }
        const unsigned aoff = (unsigned)(buf * 128 * 16 * 4);
        const float* Bb = &Bs[buf][0];
#pragma unroll
        for (int kh = 0; kh < 2; ++kh) {
            const int k = kh * 8 + (lane & 3);
            unsigned af[4][4];
#pragma unroll
            for (int mt = 0; mt < 4; ++mt)
                ldsm4(af[mt][0], af[mt][1], af[mt][2], af[mt][3], amat[mt][kh] + aoff);
#pragma unroll
            for (int nt = 0; nt < 4; ++nt) {
                int n = wn * 32 + nt * 8 + (lane >> 2);
                unsigned b0 = __float_as_uint(Bb[k * PB + n]);
                unsigned b1 = __float_as_uint(Bb[(k + 4) * PB + n]);
#pragma unroll
                for (int mt = 0; mt < 4; ++mt)
                    mma_tf32(acc[mt][nt], af[mt][0], af[mt][1], af[mt][2], af[mt][3], b0, b1);
            }
        }
        if (it + 1 < nIter) {
            int nb = buf ^ 1;
            *(float4*)&As[nb][ast0] = av0;
            *(float4*)&As[nb][ast1] = av1;
            *(float4*)&Bs[nb][bk * PB + bnc] = bv0;
            *(float4*)&Bs[nb][bk * PB + bnc + 4] = bv1;
            __syncthreads();
            buf = nb;
        }
    }

    // epilogue
    const int kvsel = (bn >= 2048) ? 1 : 0;
#pragma unroll
    for (int mt = 0; mt < 4; ++mt) {
        int row0 = bm + wm * 64 + mt * 16 + (lane >> 2);
#pragma unroll
        for (int nt = 0; nt < 4; ++nt) {
            int col = bn + wn * 32 + nt * 8 + 2 * (lane & 3);
            float2 bv = *(const float2*)&bias[col];
            float v00 = acc[mt][nt][0] + bv.x, v01 = acc[mt][nt][1] + bv.y;
            float v10 = acc[mt][nt][2] + bv.x, v11 = acc[mt][nt][3] + bv.y;
            if (mode == 0) {
                float2 r0 = {v00, v01}, r1 = {v10, v11};
                *(float2*)&C[(long)row0 * N + col] = r0;
                *(float2*)&C[(long)(row0 + 8) * N + col] = r1;
            } else if (bn < 1024) {
                const float sc = 0.125f * LOG2E;
                float2 r0, r1;
                r0.x = __uint_as_float(f2tf(v00 * sc));
                r0.y = __uint_as_float(f2tf(v01 * sc));
                r1.x = __uint_as_float(f2tf(v10 * sc));
                r1.y = __uint_as_float(f2tf(v11 * sc));
                *(float2*)&C[(long)row0 * 1024 + col] = r0;
                *(float2*)&C[(long)(row0 + 8) * 1024 + col] = r1;
            } else {
                int colk = col - 1024 - (kvsel << 10);
                int h = colk >> 6, d = colk & 63;
                int b = row0 >> 10, s = row0 & 1023;
                long o0 = ((((long)(kvsel * 4 + b) * 16 + h) * 2048) + 1024 + s) * 64 + d;
                long o1 = o0 + 8 * 64;
                float2 p0 = {v00, v01}, p1 = {v10, v11};
                *(float2*)&present[o0] = p0;
                *(float2*)&present[o1] = p1;
                float2 t0, t1;
                t0.x = __uint_as_float(f2tf(v00));
                t0.y = __uint_as_float(f2tf(v01));
                t1.x = __uint_as_float(f2tf(v10));
                t1.y = __uint_as_float(f2tf(v11));
                *(float2*)&kvt[o0] = t0;
                *(float2*)&kvt[o1] = t1;
            }
        }
    }
}

// ---------------------------------------------------------------------------
// Copy the PAST half of present (+ rounded copy). New half written by gemm3.
// ---------------------------------------------------------------------------
__global__ __launch_bounds__(256) void copy_past_kernel(
    const float* __restrict__ past, float* __restrict__ present,
    float* __restrict__ kvt)
{
    int i4 = blockIdx.x * 256 + threadIdx.x;  // 0 .. 2097151
    int d4 = i4 & 15;
    int t = i4 >> 4;
    int p = t & 1023; t >>= 10;
    int h = t & 15;   t >>= 4;
    int b = t & 3;    t >>= 2;
    int kv = t;

    float4 v = *(const float4*)&past[(((long)(kv * 4 + b) * 16 + h) * 1024 + p) * 64 + d4 * 4];
    long dst = ((((long)(kv * 4 + b) * 16 + h) * 2048) + p) * 64 + d4 * 4;
    *(float4*)&present[dst] = v;
    float4 r;
    r.x = __uint_as_float(f2tf(v.x));
    r.y = __uint_as_float(f2tf(v.y));
    r.z = __uint_as_float(f2tf(v.z));
    r.w = __uint_as_float(f2tf(v.w));
    *(float4*)&kvt[dst] = r;
}

// ---------------------------------------------------------------------------
// Flash attention (unchanged from R5): tf32 mma, cp.async K/V double buffer,
// pre-scaled tf32 Q from g_q, shuffle-P, exp2 softmax, tf32-rounded output.
// ---------------------------------------------------------------------------
#define QKP 68
#define VST 72

__global__ __launch_bounds__(256, 2) void attn_kernel(
    const float* __restrict__ gq,
    const float* __restrict__ kvt,
    float* __restrict__ aout)
{
    extern __shared__ float sm[];
    float* Qs = sm;                         // [128][68]
    float* Ks = Qs + 128 * QKP;             // [2][64][68]
    float* Vs = Ks + 2 * 64 * QKP;          // [2][64][72]

    const int tid = threadIdx.x;
    const int lane = tid & 31;
    const int w = tid >> 5;
    const int qt = blockIdx.x & 7;
    const int h  = (blockIdx.x >> 3) & 15;
    const int b  = blockIdx.x >> 7;

    const float* kbase = kvt + (long)(b * 16 + h) * (2048 * 64);
    const float* vbase = kbase + (long)4 * 16 * 2048 * 64;

    const unsigned qs_base = (unsigned)__cvta_generic_to_shared(Qs);
    const unsigned ks_base = (unsigned)__cvta_generic_to_shared(Ks);
    const unsigned vs_base = (unsigned)__cvta_generic_to_shared(Vs);

    auto stage = [&](int kt, int bf) {
        const float* kp = kbase + (long)kt * 64 * 64;
        const float* vp = vbase + (long)kt * 64 * 64;
        unsigned kd = ks_base + (unsigned)(bf * 64 * QKP * 4);
        unsigned vd = vs_base + (unsigned)(bf * 64 * VST * 4);
#pragma unroll
        for (int l = 0; l < 4; ++l) {
            int idx = l * 256 + tid;
            int r = idx >> 4, c4 = (idx & 15) * 4;
            cp16(kd + (unsigned)((r * QKP + c4) * 4), kp + idx * 4);
            cp16(vd + (unsigned)((r * VST + c4) * 4), vp + idx * 4);
        }
    };

    {
        const float* qb = gq + ((long)b * 1024 + qt * 128) * 1024 + h * 64;
#pragma unroll
        for (int l = 0; l < 8; ++l) {
            int idx = l * 256 + tid;
            int r = idx >> 4, c4 = (idx & 15) * 4;
            cp16(qs_base + (unsigned)((r * QKP + c4) * 4), qb + (long)r * 1024 + c4);
        }
    }
    stage(0, 0); cp_commit();
    stage(1, 1); cp_commit();
    cp_wait1();
    __syncthreads();

    const int diag0 = 16 + 2 * qt;
    const int nkt = diag0 + 2;

    unsigned qf[8][4];
    {
        int r = 16 * w + (lane >> 2);
#pragma unroll
        for (int kk = 0; kk < 8; ++kk) {
            int k = kk * 8 + (lane & 3);
            qf[kk][0] = __float_as_uint(Qs[r * QKP + k]);
            qf[kk][1] = __float_as_uint(Qs[(r + 8) * QKP + k]);
            qf[kk][2] = __float_as_uint(Qs[r * QKP + k + 4]);
            qf[kk][3] = __float_as_uint(Qs[(r + 8) * QKP + k + 4]);
        }
    }

    float o[8][4] = {};
    float m0 = -1e30f, m1 = -1e30f, l0 = 0.f, l1 = 0.f;

    const int src_a = (lane & ~3) | ((lane & 3) >> 1);
    const int src_b = src_a + 2;

    for (int kt = 0; kt < nkt; ++kt) {
        const int bf = kt & 1;
        const float* Kb = Ks + bf * 64 * QKP;
        const float* Vb = Vs + bf * 64 * VST;

        float s[8][4] = {};
#pragma unroll
        for (int kk = 0; kk < 8; ++kk) {
            int k = kk * 8 + (lane & 3);
#pragma unroll
            for (int nt = 0; nt < 8; ++nt) {
                int n = nt * 8 + (lane >> 2);
                unsigned b0 = __float_as_uint(Kb[n * QKP + k]);
                unsigned b1 = __float_as_uint(Kb[n * QKP + k + 4]);
                mma_tf32(s[nt], qf[kk][0], qf[kk][1], qf[kk][2], qf[kk][3], b0, b1);
            }
        }

        if (kt >= diag0) {
            int q0 = 1024 + qt * 128 + 16 * w + (lane >> 2);
            int q1 = q0 + 8;
#pragma unroll
            for (int nt = 0; nt < 8; ++nt) {
                int kc = kt * 64 + nt * 8 + 2 * (lane & 3);
                if (kc > q0)     s[nt][0] = -14427.0f;
                if (kc + 1 > q0) s[nt][1] = -14427.0f;
                if (kc > q1)     s[nt][2] = -14427.0f;
                if (kc + 1 > q1) s[nt][3] = -14427.0f;
            }
        }

        {
            float mt0 = -1e30f, mt1 = -1e30f;
#pragma unroll
            for (int nt = 0; nt < 8; ++nt) {
                mt0 = fmaxf(mt0, fmaxf(s[nt][0], s[nt][1]));
                mt1 = fmaxf(mt1, fmaxf(s[nt][2], s[nt][3]));
            }
            mt0 = fmaxf(mt0, __shfl_xor_sync(0xffffffffu, mt0, 1));
            mt0 = fmaxf(mt0, __shfl_xor_sync(0xffffffffu, mt0, 2));
            mt1 = fmaxf(mt1, __shfl_xor_sync(0xffffffffu, mt1, 1));
            mt1 = fmaxf(mt1, __shfl_xor_sync(0xffffffffu, mt1, 2));
            float mn0 = fmaxf(m0, mt0), mn1 = fmaxf(m1, mt1);
            float c0 = ex2(m0 - mn0), c1 = ex2(m1 - mn1);
            m0 = mn0; m1 = mn1;
            float rs0 = 0.f, rs1 = 0.f;
#pragma unroll
            for (int nt = 0; nt < 8; ++nt) {
                s[nt][0] = ex2(s[nt][0] - mn0);
                s[nt][1] = ex2(s[nt][1] - mn0);
                s[nt][2] = ex2(s[nt][2] - mn1);
                s[nt][3] = ex2(s[nt][3] - mn1);
                rs0 += s[nt][0] + s[nt][1];
                rs1 += s[nt][2] + s[nt][3];
            }
            rs0 += __shfl_xor_sync(0xffffffffu, rs0, 1);
            rs0 += __shfl_xor_sync(0xffffffffu, rs0, 2);
            rs1 += __shfl_xor_sync(0xffffffffu, rs1, 1);
            rs1 += __shfl_xor_sync(0xffffffffu, rs1, 2);
            l0 = l0 * c0 + rs0;
            l1 = l1 * c1 + rs1;
#pragma unroll
            for (int dt = 0; dt < 8; ++dt) {
                o[dt][0] *= c0; o[dt][1] *= c0;
                o[dt][2] *= c1; o[dt][3] *= c1;
            }
        }

#pragma unroll
        for (int kk = 0; kk < 8; ++kk) {
            float x0 = __shfl_sync(0xffffffffu, s[kk][0], src_a);
            float x1 = __shfl_sync(0xffffffffu, s[kk][1], src_a);
            float y0 = __shfl_sync(0xffffffffu, s[kk][2], src_a);
            float y1 = __shfl_sync(0xffffffffu, s[kk][3], src_a);
            float z0 = __shfl_sync(0xffffffffu, s[kk][0], src_b);
            float z1 = __shfl_sync(0xffffffffu, s[kk][1], src_b);
            float u0 = __shfl_sync(0xffffffffu, s[kk][2], src_b);
            float u1 = __shfl_sync(0xffffffffu, s[kk][3], src_b);
            bool odd = (lane & 1);
            unsigned a0 = f2tf(odd ? x1 : x0);
            unsigned a1 = f2tf(odd ? y1 : y0);
            unsigned a2 = f2tf(odd ? z1 : z0);
            unsigned a3 = f2tf(odd ? u1 : u0);
            int kb0 = (kk * 8 + (lane & 3)) * VST;
            int kb1 = (kk * 8 + (lane & 3) + 4) * VST;
#pragma unroll
            for (int dt = 0; dt < 8; ++dt) {
                int n = dt * 8 + (lane >> 2);
                unsigned b0 = __float_as_uint(Vb[kb0 + n]);
                unsigned b1 = __float_as_uint(Vb[kb1 + n]);
                mma_tf32(o[dt], a0, a1, a2, a3, b0, b1);
            }
        }

        if (kt + 1 < nkt) {
            __syncthreads();
            if (kt + 2 < nkt) stage(kt + 2, bf);
            cp_commit();
            cp_wait1();
            __syncthreads();
        }
    }

    {
        float inv0 = 1.0f / l0, inv1 = 1.0f / l1;
        int row0 = b * 1024 + qt * 128 + 16 * w + (lane >> 2);
        float* ob = aout + (long)row0 * 1024 + h * 64;
#pragma unroll
        for (int dt = 0; dt < 8; ++dt) {
            int c = dt * 8 + 2 * (lane & 3);
            float2 v0, v1;
            v0.x = __uint_as_float(f2tf(o[dt][0] * inv0));
            v0.y = __uint_as_float(f2tf(o[dt][1] * inv0));
            v1.x = __uint_as_float(f2tf(o[dt][2] * inv1));
            v1.y = __uint_as_float(f2tf(o[dt][3] * inv1));
            *(float2*)&ob[c] = v0;
            *(float2*)&ob[(long)8 * 1024 + c] = v1;
        }
    }
}

// ---------------------------------------------------------------------------
extern "C" void kernel_launch(void* const* d_in, const int* in_sizes, int n_in,
                              void* d_out, int out_size)
{
    const float* x      = (const float*)d_in[0];
    const float* past   = (const float*)d_in[1];
    const float* w_attn = (const float*)d_in[2];
    const float* b_attn = (const float*)d_in[3];
    const float* w_proj = (const float*)d_in[4];
    const float* b_proj = (const float*)d_in[5];

    float* out = (float*)d_out;
    float* present = out + 4194304;

    float *q_p, *attn_p, *kvt_p, *xr_p, *wat_p, *wpr_p;
    cudaGetSymbolAddress((void**)&q_p, g_q);
    cudaGetSymbolAddress((void**)&attn_p, g_attn);
    cudaGetSymbolAddress((void**)&kvt_p, g_kvt);
    cudaGetSymbolAddress((void**)&xr_p, g_xr);
    cudaGetSymbolAddress((void**)&wat_p, g_wat);
    cudaGetSymbolAddress((void**)&wpr_p, g_wpr);

    // 0) pre-round GEMM operands to tf32
    round_tf32_kernel<<<4096, 256>>>(x, xr_p);
    round_tf32_kernel<<<3072, 256>>>(w_attn, wat_p);
    round_tf32_kernel<<<1024, 256>>>(w_proj, wpr_p);

    // 1) QKV projection with fused Q-scale / present / kvt epilogue
    {
        dim3 grid(3072 / 128, 4096 / 128);
        gemm3_kernel<<<grid, 256>>>(xr_p, wat_p, b_attn, q_p,
                                    present, kvt_p, 4096, 3072, 1024, 1);
    }

    // 2) past half of present/kvt
    copy_past_kernel<<<2097152 / 256, 256>>>(past, present, kvt_p);

    // 3) attention
    {
        int smem = (128 * QKP + 2 * 64 * QKP + 2 * 64 * VST) * (int)sizeof(float);
        cudaFuncSetAttribute(attn_kernel,
                             cudaFuncAttributeMaxDynamicSharedMemorySize, smem);
        attn_kernel<<<512, 256, smem>>>(q_p, kvt_p, attn_p);
    }

    // 4) output projection
    {
        dim3 grid(1024 / 128, 4096 / 128);
        gemm3_kernel<<<grid, 256>>>(attn_p, wpr_p, b_proj, out,
                                    nullptr, nullptr, 4096, 1024, 1024, 0);
    }
}